// round 2
// baseline (speedup 1.0000x reference)
#include <cuda_runtime.h>
#include <cstdint>

#define N_NODES 100000
#define E_EDGES 1600000
#define DIM 128

// Scratch (allocation-free rule: device globals)
__device__ float g_h[(size_t)N_NODES * DIM];    // ori = x@W^T + b
__device__ float g_t[(size_t)N_NODES * DIM];    // relu(ln(...)) activations
__device__ float g_acc[(size_t)N_NODES * DIM];  // layer-0 aggregation
__device__ int   g_src[E_EDGES];
__device__ int   g_dst[E_EDGES];
__device__ int   g_is64;

// ---- detect whether edge_index buffer is int64 (hi words all zero) --------
__global__ void detect_kernel(const int* __restrict__ raw) {
    int is64 = 1;
    for (int i = 0; i < 64; i++) {
        if (raw[2 * i + 1] != 0) { is64 = 0; break; }
    }
    g_is64 = is64;
}

// ---- expand edge_index (int32 or int64 layout) into int32 src/dst --------
__global__ void convert_kernel(const int* __restrict__ raw) {
    int e = blockIdx.x * blockDim.x + threadIdx.x;
    if (e >= E_EDGES) return;
    int s, d;
    if (g_is64) {
        s = raw[2 * (size_t)e];
        d = raw[2 * ((size_t)E_EDGES + e)];
    } else {
        s = raw[e];
        d = raw[E_EDGES + e];
    }
    // defensive clamp: wrong values -> wrong result (visible), never a crash
    s = min(max(s, 0), N_NODES - 1);
    d = min(max(d, 0), N_NODES - 1);
    g_src[e] = s;
    g_dst[e] = d;
}

// ---------------- GEMM: h = x @ W^T + b  (W is [128,128]) ------------------
__global__ void gemm_kernel(const float* __restrict__ x,
                            const float* __restrict__ W,
                            const float* __restrict__ b,
                            float* __restrict__ out) {
    int warp = threadIdx.x >> 5;
    int lane = threadIdx.x & 31;
    int row = blockIdx.x * 8 + warp;
    if (row >= N_NODES) return;

    __shared__ float4 xs[8][32];
    const float4* xr = (const float4*)(x + (size_t)row * DIM);
    xs[warp][lane] = xr[lane];
    __syncwarp();

    float acc[4];
#pragma unroll
    for (int c = 0; c < 4; c++) {
        int col = lane * 4 + c;
        const float4* wr = (const float4*)(W + (size_t)col * DIM);
        float s = __ldg(b + col);
#pragma unroll 8
        for (int k = 0; k < 32; k++) {
            float4 w = wr[k];
            float4 xv = xs[warp][k];
            s = fmaf(xv.x, w.x, s);
            s = fmaf(xv.y, w.y, s);
            s = fmaf(xv.z, w.z, s);
            s = fmaf(xv.w, w.w, s);
        }
        acc[c] = s;
    }
    ((float4*)(out + (size_t)row * DIM))[lane] =
        make_float4(acc[0], acc[1], acc[2], acc[3]);
}

// ------------- LayerNorm (+optional residual) + ReLU, warp per row ---------
__global__ void ln_relu_kernel(const float* __restrict__ hin,
                               const float* __restrict__ ori,  // may be null
                               const float* __restrict__ scale,
                               const float* __restrict__ bias,
                               float* __restrict__ out) {
    int warp = threadIdx.x >> 5;
    int lane = threadIdx.x & 31;
    int row = blockIdx.x * 8 + warp;
    if (row >= N_NODES) return;
    size_t base = (size_t)row * DIM;

    float4 v = ((const float4*)(hin + base))[lane];
    if (ori != nullptr) {
        float4 o = ((const float4*)(ori + base))[lane];
        v.x += o.x; v.y += o.y; v.z += o.z; v.w += o.w;
    }
    float s = v.x + v.y + v.z + v.w;
#pragma unroll
    for (int off = 16; off; off >>= 1) s += __shfl_xor_sync(0xffffffffu, s, off);
    float mu = s * (1.0f / 128.0f);

    float dx = v.x - mu, dy = v.y - mu, dz = v.z - mu, dw = v.w - mu;
    float q = dx * dx + dy * dy + dz * dz + dw * dw;
#pragma unroll
    for (int off = 16; off; off >>= 1) q += __shfl_xor_sync(0xffffffffu, q, off);
    float rstd = rsqrtf(q * (1.0f / 128.0f) + 1e-5f);

    float4 sc = ((const float4*)scale)[lane];
    float4 bi = ((const float4*)bias)[lane];
    float4 r;
    r.x = fmaxf(fmaf(dx * rstd, sc.x, bi.x), 0.0f);
    r.y = fmaxf(fmaf(dy * rstd, sc.y, bi.y), 0.0f);
    r.z = fmaxf(fmaf(dz * rstd, sc.z, bi.z), 0.0f);
    r.w = fmaxf(fmaf(dw * rstd, sc.w, bi.w), 0.0f);
    ((float4*)(out + base))[lane] = r;
}

// -------------------- zero a float buffer (float4 stores) ------------------
__global__ void zero_kernel(float4* __restrict__ p, int n4) {
    int i = blockIdx.x * blockDim.x + threadIdx.x;
    if (i < n4) p[i] = make_float4(0.f, 0.f, 0.f, 0.f);
}

// ------------- SpMM scatter: acc[dst] += t[src] * e_feat, warp per edge ----
__global__ void scatter_kernel(const float* __restrict__ t,
                               const float* __restrict__ ef,
                               float* __restrict__ acc) {
    int warp = threadIdx.x >> 5;
    int lane = threadIdx.x & 31;
    int e = blockIdx.x * 8 + warp;
    if (e >= E_EDGES) return;

    int src = g_src[e];
    int dst = g_dst[e];
    float w = __ldg(ef + e);

    float4 v = ((const float4*)(t + (size_t)src * DIM))[lane];
    v.x *= w; v.y *= w; v.z *= w; v.w *= w;

    float* addr = acc + (size_t)dst * DIM + lane * 4;
    asm volatile("red.global.add.v4.f32 [%0], {%1,%2,%3,%4};"
                 :: "l"(addr), "f"(v.x), "f"(v.y), "f"(v.z), "f"(v.w)
                 : "memory");
}

extern "C" void kernel_launch(void* const* d_in, const int* in_sizes, int n_in,
                              void* d_out, int out_size) {
    // Bind inputs by element count (robust to metadata ordering).
    const float* x = nullptr;
    const int*   ei_raw = nullptr;
    const float* ef = nullptr;
    const float* lin_w = nullptr;
    const float* lin_b = nullptr;
    const float* ln_scale = nullptr;
    const float* ln_bias = nullptr;
    for (int i = 0; i < n_in; i++) {
        switch (in_sizes[i]) {
            case N_NODES * DIM:      x      = (const float*)d_in[i]; break;
            case 2 * E_EDGES:        ei_raw = (const int*)d_in[i];   break;
            case E_EDGES:            ef     = (const float*)d_in[i]; break;
            case DIM * DIM:          lin_w  = (const float*)d_in[i]; break;
            case DIM:                lin_b  = (const float*)d_in[i]; break;
            case 2 * DIM:
                if (!ln_scale) ln_scale = (const float*)d_in[i];
                else           ln_bias  = (const float*)d_in[i];
                break;
            default: break;
        }
    }
    float* out = (float*)d_out;

    float *h, *t, *acc;
    cudaGetSymbolAddress((void**)&h,   g_h);
    cudaGetSymbolAddress((void**)&t,   g_t);
    cudaGetSymbolAddress((void**)&acc, g_acc);

    const int ROWS_GRID = (N_NODES + 7) / 8;   // warp per row, 8 warps/block
    const int EDGE_GRID = (E_EDGES + 7) / 8;   // warp per edge
    const int N4        = N_NODES * DIM / 4;
    const int ZERO_GRID = (N4 + 255) / 256;

    // edge index preprocessing (cheap; inside graph, deterministic)
    detect_kernel<<<1, 1>>>(ei_raw);
    convert_kernel<<<(E_EDGES + 255) / 256, 256>>>(ei_raw);

    // h = x @ W^T + b   (this is "ori")
    gemm_kernel<<<ROWS_GRID, 256>>>(x, lin_w, lin_b, h);

    // ---- layer 0 ----
    ln_relu_kernel<<<ROWS_GRID, 256>>>(h, nullptr, ln_scale, ln_bias, t);
    zero_kernel<<<ZERO_GRID, 256>>>((float4*)acc, N4);
    scatter_kernel<<<EDGE_GRID, 256>>>(t, ef, acc);

    // ---- layer 1 (residual + ln params row 1) ----
    ln_relu_kernel<<<ROWS_GRID, 256>>>(acc, h, ln_scale + DIM, ln_bias + DIM, t);
    zero_kernel<<<ZERO_GRID, 256>>>((float4*)out, N4);
    scatter_kernel<<<EDGE_GRID, 256>>>(t, ef, out);
}

// round 3
// speedup vs baseline: 8.2049x; 8.2049x over previous
#include <cuda_runtime.h>
#include <cstdint>

#define N_NODES 100000
#define E_EDGES 1600000
#define DIM 128
#define FULL 0xffffffffu

// ------------------------- device scratch (no allocs) ----------------------
__device__ float g_h[(size_t)N_NODES * DIM];    // ori = x@W^T + b
__device__ float g_t[(size_t)N_NODES * DIM];    // relu(ln0(h))
__device__ float g_t2[(size_t)N_NODES * DIM];   // relu(ln1(agg0 + h))
__device__ int   g_src[E_EDGES];
__device__ int   g_dst[E_EDGES];
__device__ int   g_cs[E_EDGES];                 // CSR: src sorted by dst
__device__ float g_cw[E_EDGES];                 // CSR: weight sorted by dst
__device__ int   g_deg[N_NODES];
__device__ int   g_off[N_NODES + 1];
__device__ int   g_cursor[N_NODES];
__device__ int   g_is64;

// ---- detect whether edge_index buffer is int64 (hi words all zero) --------
__global__ void detect_kernel(const int* __restrict__ raw) {
    int is64 = 1;
    for (int i = 0; i < 64; i++) {
        if (raw[2 * i + 1] != 0) { is64 = 0; break; }
    }
    g_is64 = is64;
}

__global__ void zero_deg_kernel() {
    int i = blockIdx.x * blockDim.x + threadIdx.x;
    if (i < N_NODES) g_deg[i] = 0;
}

// ---- expand edge_index into int32 src/dst + histogram dst degrees ---------
__global__ void convert_hist_kernel(const int* __restrict__ raw) {
    int e = blockIdx.x * blockDim.x + threadIdx.x;
    if (e >= E_EDGES) return;
    int s, d;
    if (g_is64) {
        s = raw[2 * (size_t)e];
        d = raw[2 * ((size_t)E_EDGES + e)];
    } else {
        s = raw[e];
        d = raw[E_EDGES + e];
    }
    s = min(max(s, 0), N_NODES - 1);
    d = min(max(d, 0), N_NODES - 1);
    g_src[e] = s;
    g_dst[e] = d;
    atomicAdd(&g_deg[d], 1);
}

// ---- exclusive prefix scan of degrees (single block, 1024 threads) --------
__global__ void scan_kernel() {
    __shared__ int wsum[32];
    __shared__ int carry_s, total_s;
    int tid = threadIdx.x, lane = tid & 31, wid = tid >> 5;
    if (tid == 0) carry_s = 0;
    __syncthreads();
    for (int base = 0; base < N_NODES; base += 1024) {
        int idx = base + tid;
        int v = (idx < N_NODES) ? g_deg[idx] : 0;
        int inc = v;
#pragma unroll
        for (int o = 1; o < 32; o <<= 1) {
            int n = __shfl_up_sync(FULL, inc, o);
            if (lane >= o) inc += n;
        }
        if (lane == 31) wsum[wid] = inc;
        __syncthreads();
        if (wid == 0) {
            int w = wsum[lane];
            int wi = w;
#pragma unroll
            for (int o = 1; o < 32; o <<= 1) {
                int n = __shfl_up_sync(FULL, wi, o);
                if (lane >= o) wi += n;
            }
            wsum[lane] = wi - w;
            if (lane == 31) total_s = wi;
        }
        __syncthreads();
        int excl = carry_s + wsum[wid] + (inc - v);
        if (idx < N_NODES) { g_off[idx] = excl; g_cursor[idx] = excl; }
        __syncthreads();
        if (tid == 0) carry_s += total_s;
        __syncthreads();
    }
    if (tid == 0) g_off[N_NODES] = E_EDGES;
}

// ---- fill CSR buckets -----------------------------------------------------
__global__ void fill_kernel(const float* __restrict__ ef) {
    int e = blockIdx.x * blockDim.x + threadIdx.x;
    if (e >= E_EDGES) return;
    int d = g_dst[e];
    int pos = atomicAdd(&g_cursor[d], 1);
    g_cs[pos] = g_src[e];
    g_cw[pos] = ef[e];
}

// ---- GEMM (h = x @ W^T + b) fused with LN0 + ReLU -------------------------
// Block: 256 threads = 8 warps; warp handles 8 rows; block 64 rows.
// Lane holds cols {lane, 32+lane, 64+lane, 96+lane}.
// Dynamic smem: Ws[32][132] float4 (k4-major, padded) + Xs[8][8][32] float4.
#define WS_PITCH 132
__global__ void gemm_ln_kernel(const float* __restrict__ x,
                               const float* __restrict__ W,
                               const float* __restrict__ b,
                               const float* __restrict__ scale,
                               const float* __restrict__ bias,
                               float* __restrict__ h_out,
                               float* __restrict__ t_out) {
    extern __shared__ float4 smem[];
    float4* Ws = smem;                      // [k4][col] pitch WS_PITCH
    float4* Xs = smem + 32 * WS_PITCH;      // [warp*8 + r][k4]

    int tid = threadIdx.x, lane = tid & 31, warp = tid >> 5;
    int rowBase = blockIdx.x * 64 + warp * 8;

    // load W: 4096 float4, coalesced (f4 index = col*32 + k4 = tid-linear)
    for (int idx = tid; idx < DIM * 32; idx += 256) {
        int col = idx >> 5, k4 = idx & 31;
        Ws[k4 * WS_PITCH + col] = ((const float4*)W)[idx];
    }
    // load X: 8 rows per warp
    for (int r = 0; r < 8; r++) {
        int row = rowBase + r;
        float4 v = make_float4(0.f, 0.f, 0.f, 0.f);
        if (row < N_NODES) v = ((const float4*)x)[(size_t)row * 32 + lane];
        Xs[(warp * 8 + r) * 32 + lane] = v;
    }
    __syncthreads();

    float acc[8][4];
#pragma unroll
    for (int r = 0; r < 8; r++)
#pragma unroll
        for (int c = 0; c < 4; c++) acc[r][c] = 0.f;

    for (int k4 = 0; k4 < 32; k4++) {
        float4 xv[8];
#pragma unroll
        for (int r = 0; r < 8; r++) xv[r] = Xs[(warp * 8 + r) * 32 + k4];
#pragma unroll
        for (int c = 0; c < 4; c++) {
            float4 wv = Ws[k4 * WS_PITCH + c * 32 + lane];
#pragma unroll
            for (int r = 0; r < 8; r++) {
                acc[r][c] = fmaf(xv[r].x, wv.x, acc[r][c]);
                acc[r][c] = fmaf(xv[r].y, wv.y, acc[r][c]);
                acc[r][c] = fmaf(xv[r].z, wv.z, acc[r][c]);
                acc[r][c] = fmaf(xv[r].w, wv.w, acc[r][c]);
            }
        }
    }

    float bv[4], sv[4], biv[4];
#pragma unroll
    for (int c = 0; c < 4; c++) {
        bv[c]  = __ldg(b + c * 32 + lane);
        sv[c]  = __ldg(scale + c * 32 + lane);
        biv[c] = __ldg(bias + c * 32 + lane);
    }

#pragma unroll
    for (int r = 0; r < 8; r++) {
        int row = rowBase + r;
        if (row >= N_NODES) break;
        float v[4];
#pragma unroll
        for (int c = 0; c < 4; c++) v[c] = acc[r][c] + bv[c];
        float s = v[0] + v[1] + v[2] + v[3];
#pragma unroll
        for (int o = 16; o; o >>= 1) s += __shfl_xor_sync(FULL, s, o);
        float mu = s * (1.0f / 128.0f);
        float q = 0.f;
#pragma unroll
        for (int c = 0; c < 4; c++) {
            float d = v[c] - mu;
            q += d * d;
        }
#pragma unroll
        for (int o = 16; o; o >>= 1) q += __shfl_xor_sync(FULL, q, o);
        float rstd = rsqrtf(q * (1.0f / 128.0f) + 1e-5f);
        size_t base = (size_t)row * DIM;
#pragma unroll
        for (int c = 0; c < 4; c++) {
            h_out[base + c * 32 + lane] = v[c];
            float t = fmaf((v[c] - mu) * rstd, sv[c], biv[c]);
            t_out[base + c * 32 + lane] = fmaxf(t, 0.0f);
        }
    }
}

// ---- CSR aggregation: acc[dst] = sum_e w * t[src]; optional fused LN ------
template <bool FUSE_LN>
__global__ void agg_kernel(const float* __restrict__ t,
                           const float* __restrict__ hres,   // residual (FUSE_LN)
                           const float* __restrict__ scale,
                           const float* __restrict__ bias,
                           float* __restrict__ out) {
    int warp = threadIdx.x >> 5;
    int lane = threadIdx.x & 31;
    int row = blockIdx.x * 8 + warp;
    if (row >= N_NODES) return;

    int beg = g_off[row], end = g_off[row + 1];
    float4 acc = make_float4(0.f, 0.f, 0.f, 0.f);
    for (int i = beg; i < end; i++) {
        int s = g_cs[i];                 // warp-uniform load
        float w = g_cw[i];               // warp-uniform load
        float4 v = ((const float4*)(t + (size_t)s * DIM))[lane];
        acc.x = fmaf(w, v.x, acc.x);
        acc.y = fmaf(w, v.y, acc.y);
        acc.z = fmaf(w, v.z, acc.z);
        acc.w = fmaf(w, v.w, acc.w);
    }

    size_t base = (size_t)row * DIM;
    if (FUSE_LN) {
        float4 o = ((const float4*)(hres + base))[lane];
        acc.x += o.x; acc.y += o.y; acc.z += o.z; acc.w += o.w;
        float s = acc.x + acc.y + acc.z + acc.w;
#pragma unroll
        for (int o2 = 16; o2; o2 >>= 1) s += __shfl_xor_sync(FULL, s, o2);
        float mu = s * (1.0f / 128.0f);
        float dx = acc.x - mu, dy = acc.y - mu, dz = acc.z - mu, dw = acc.w - mu;
        float q = dx * dx + dy * dy + dz * dz + dw * dw;
#pragma unroll
        for (int o2 = 16; o2; o2 >>= 1) q += __shfl_xor_sync(FULL, q, o2);
        float rstd = rsqrtf(q * (1.0f / 128.0f) + 1e-5f);
        float4 sc = ((const float4*)scale)[lane];
        float4 bi = ((const float4*)bias)[lane];
        float4 r;
        r.x = fmaxf(fmaf(dx * rstd, sc.x, bi.x), 0.0f);
        r.y = fmaxf(fmaf(dy * rstd, sc.y, bi.y), 0.0f);
        r.z = fmaxf(fmaf(dz * rstd, sc.z, bi.z), 0.0f);
        r.w = fmaxf(fmaf(dw * rstd, sc.w, bi.w), 0.0f);
        ((float4*)(out + base))[lane] = r;
    } else {
        ((float4*)(out + base))[lane] = acc;
    }
}

extern "C" void kernel_launch(void* const* d_in, const int* in_sizes, int n_in,
                              void* d_out, int out_size) {
    // Bind inputs by element count.
    const float* x = nullptr;
    const int*   ei_raw = nullptr;
    const float* ef = nullptr;
    const float* lin_w = nullptr;
    const float* lin_b = nullptr;
    const float* ln_scale = nullptr;
    const float* ln_bias = nullptr;
    for (int i = 0; i < n_in; i++) {
        switch (in_sizes[i]) {
            case N_NODES * DIM: x      = (const float*)d_in[i]; break;
            case 2 * E_EDGES:   ei_raw = (const int*)d_in[i];   break;
            case E_EDGES:       ef     = (const float*)d_in[i]; break;
            case DIM * DIM:     lin_w  = (const float*)d_in[i]; break;
            case DIM:           lin_b  = (const float*)d_in[i]; break;
            case 2 * DIM:
                if (!ln_scale) ln_scale = (const float*)d_in[i];
                else           ln_bias  = (const float*)d_in[i];
                break;
            default: break;
        }
    }
    float* out = (float*)d_out;

    float *h, *t, *t2;
    cudaGetSymbolAddress((void**)&h,  g_h);
    cudaGetSymbolAddress((void**)&t,  g_t);
    cudaGetSymbolAddress((void**)&t2, g_t2);

    const int EDGE_BLKS = (E_EDGES + 255) / 256;
    const int NODE_BLKS = (N_NODES + 255) / 256;
    const int ROWS_GRID = (N_NODES + 7) / 8;         // warp per row
    const int GEMM_GRID = (N_NODES + 63) / 64;
    const int GEMM_SMEM = (32 * WS_PITCH + 8 * 8 * 32) * sizeof(float4);

    static bool attr_done = false;
    if (!attr_done) {
        cudaFuncSetAttribute(gemm_ln_kernel,
                             cudaFuncAttributeMaxDynamicSharedMemorySize,
                             GEMM_SMEM);
        attr_done = true;
    }

    // ---- CSR build (per call; deterministic work) ----
    detect_kernel<<<1, 1>>>(ei_raw);
    zero_deg_kernel<<<NODE_BLKS, 256>>>();
    convert_hist_kernel<<<EDGE_BLKS, 256>>>(ei_raw);
    scan_kernel<<<1, 1024>>>();
    fill_kernel<<<EDGE_BLKS, 256>>>(ef);

    // ---- h = x@W^T+b ; t = relu(ln0(h)) ----
    gemm_ln_kernel<<<GEMM_GRID, 256, GEMM_SMEM>>>(x, lin_w, lin_b,
                                                  ln_scale, ln_bias, h, t);

    // ---- layer 0 agg + residual + LN1 + ReLU -> t2 ----
    agg_kernel<true><<<ROWS_GRID, 256>>>(t, h, ln_scale + DIM, ln_bias + DIM, t2);

    // ---- layer 1 agg -> out ----
    agg_kernel<false><<<ROWS_GRID, 256>>>(t2, nullptr, nullptr, nullptr, out);
}

// round 4
// speedup vs baseline: 10.9108x; 1.3298x over previous
#include <cuda_runtime.h>
#include <cstdint>

#define N_NODES 100000
#define E_EDGES 1600000
#define DIM 128
#define FULL 0xffffffffu
#define SCAN_BLOCKS 98   // 98 * 1024 >= N_NODES

// ------------------------- device scratch (no allocs) ----------------------
__device__ float g_h[(size_t)N_NODES * DIM];    // ori = x@W^T + b
__device__ float g_t[(size_t)N_NODES * DIM];    // relu(ln0(h))
__device__ float g_t2[(size_t)N_NODES * DIM];   // relu(ln1(agg0 + h))
__device__ int   g_src[E_EDGES];
__device__ int   g_dst[E_EDGES];
__device__ int   g_cs[E_EDGES];                 // CSR: src sorted by dst
__device__ float g_cw[E_EDGES];                 // CSR: weight sorted by dst
__device__ int   g_deg[N_NODES];
__device__ int   g_off[N_NODES + 1];
__device__ int   g_cursor[N_NODES];
__device__ int   g_bsum[128];
__device__ int   g_boff[128];
__device__ int   g_is64;

// ---- f32x2 packed helpers (sm_103a FFMA2 path) ----------------------------
__device__ __forceinline__ unsigned long long pack2(float a, float b) {
    unsigned long long r;
    asm("mov.b64 %0, {%1, %2};" : "=l"(r) : "f"(a), "f"(b));
    return r;
}
__device__ __forceinline__ void fma2(unsigned long long& d,
                                     unsigned long long a,
                                     unsigned long long b) {
    asm("fma.rn.f32x2 %0, %1, %2, %0;" : "+l"(d) : "l"(a), "l"(b));
}
__device__ __forceinline__ float2 unpack2(unsigned long long v) {
    float2 r;
    asm("mov.b64 {%0, %1}, %2;" : "=f"(r.x), "=f"(r.y) : "l"(v));
    return r;
}

// ---- detect whether edge_index buffer is int64 (hi words all zero) --------
__global__ void detect_kernel(const int* __restrict__ raw) {
    int is64 = 1;
    for (int i = 0; i < 64; i++) {
        if (raw[2 * i + 1] != 0) { is64 = 0; break; }
    }
    g_is64 = is64;
}

__global__ void zero_deg_kernel() {
    int i = blockIdx.x * blockDim.x + threadIdx.x;
    if (i < N_NODES) g_deg[i] = 0;
}

// ---- expand edge_index into int32 src/dst + histogram dst degrees ---------
__global__ void convert_hist_kernel(const int* __restrict__ raw) {
    int e = blockIdx.x * blockDim.x + threadIdx.x;
    if (e >= E_EDGES) return;
    int s, d;
    if (g_is64) {
        s = raw[2 * (size_t)e];
        d = raw[2 * ((size_t)E_EDGES + e)];
    } else {
        s = raw[e];
        d = raw[E_EDGES + e];
    }
    s = min(max(s, 0), N_NODES - 1);
    d = min(max(d, 0), N_NODES - 1);
    g_src[e] = s;
    g_dst[e] = d;
    atomicAdd(&g_deg[d], 1);
}

// ---- parallel scan, phase 1: per-block sums -------------------------------
__global__ void block_sum_kernel() {
    __shared__ int ws[32];
    int tid = threadIdx.x, lane = tid & 31, wid = tid >> 5;
    int idx = blockIdx.x * 1024 + tid;
    int v = (idx < N_NODES) ? g_deg[idx] : 0;
#pragma unroll
    for (int o = 16; o; o >>= 1) v += __shfl_xor_sync(FULL, v, o);
    if (lane == 0) ws[wid] = v;
    __syncthreads();
    if (wid == 0) {
        int s = ws[lane];
#pragma unroll
        for (int o = 16; o; o >>= 1) s += __shfl_xor_sync(FULL, s, o);
        if (lane == 0) g_bsum[blockIdx.x] = s;
    }
}

// ---- parallel scan, phase 2: exclusive scan of block sums (1 block) -------
__global__ void bsum_scan_kernel() {
    __shared__ int s[128];
    int tid = threadIdx.x;
    int v = (tid < SCAN_BLOCKS) ? g_bsum[tid] : 0;
    s[tid] = v;
    __syncthreads();
#pragma unroll
    for (int o = 1; o < 128; o <<= 1) {
        int t = (tid >= o) ? s[tid - o] : 0;
        __syncthreads();
        s[tid] += t;
        __syncthreads();
    }
    g_boff[tid] = s[tid] - v;   // exclusive
}

// ---- parallel scan, phase 3: block-local scan + base --------------------
__global__ void scan_apply_kernel() {
    __shared__ int wsum[32];
    int tid = threadIdx.x, lane = tid & 31, wid = tid >> 5;
    int idx = blockIdx.x * 1024 + tid;
    int v = (idx < N_NODES) ? g_deg[idx] : 0;
    int inc = v;
#pragma unroll
    for (int o = 1; o < 32; o <<= 1) {
        int n = __shfl_up_sync(FULL, inc, o);
        if (lane >= o) inc += n;
    }
    if (lane == 31) wsum[wid] = inc;
    __syncthreads();
    if (wid == 0) {
        int w = wsum[lane];
        int wi = w;
#pragma unroll
        for (int o = 1; o < 32; o <<= 1) {
            int n = __shfl_up_sync(FULL, wi, o);
            if (lane >= o) wi += n;
        }
        wsum[lane] = wi - w;   // exclusive warp offsets
    }
    __syncthreads();
    int excl = g_boff[blockIdx.x] + wsum[wid] + (inc - v);
    if (idx < N_NODES) { g_off[idx] = excl; g_cursor[idx] = excl; }
    if (idx == 0) g_off[N_NODES] = E_EDGES;
}

// ---- fill CSR buckets -----------------------------------------------------
__global__ void fill_kernel(const float* __restrict__ ef) {
    int e = blockIdx.x * blockDim.x + threadIdx.x;
    if (e >= E_EDGES) return;
    int d = g_dst[e];
    int pos = atomicAdd(&g_cursor[d], 1);
    g_cs[pos] = g_src[e];
    g_cw[pos] = ef[e];
}

// ---- GEMM (h = x @ W^T + b) fused with LN0 + ReLU, f32x2 FMA --------------
// Block: 256 threads = 8 warps; warp handles 8 rows; block 64 rows.
// Lane holds cols {lane, 32+lane, 64+lane, 96+lane}.
#define WS_PITCH 132
__global__ void gemm_ln_kernel(const float* __restrict__ x,
                               const float* __restrict__ W,
                               const float* __restrict__ b,
                               const float* __restrict__ scale,
                               const float* __restrict__ bias,
                               float* __restrict__ h_out,
                               float* __restrict__ t_out) {
    extern __shared__ float4 smem[];
    float4* Ws = smem;                      // [k4][col] pitch WS_PITCH
    float4* Xs = smem + 32 * WS_PITCH;      // [warp*8 + r][k4]

    int tid = threadIdx.x, lane = tid & 31, warp = tid >> 5;
    int rowBase = blockIdx.x * 64 + warp * 8;

    for (int idx = tid; idx < DIM * 32; idx += 256) {
        int col = idx >> 5, k4 = idx & 31;
        Ws[k4 * WS_PITCH + col] = ((const float4*)W)[idx];
    }
    for (int r = 0; r < 8; r++) {
        int row = rowBase + r;
        float4 v = make_float4(0.f, 0.f, 0.f, 0.f);
        if (row < N_NODES) v = ((const float4*)x)[(size_t)row * 32 + lane];
        Xs[(warp * 8 + r) * 32 + lane] = v;
    }
    __syncthreads();

    // packed accumulators: acc2[r][c] = (sum over even-pair, sum over odd-pair)
    unsigned long long acc2[8][4];
#pragma unroll
    for (int r = 0; r < 8; r++)
#pragma unroll
        for (int c = 0; c < 4; c++) acc2[r][c] = 0ull;

    for (int k4 = 0; k4 < 32; k4++) {
        unsigned long long xa[8], xb[8];
#pragma unroll
        for (int r = 0; r < 8; r++) {
            float4 xv = Xs[(warp * 8 + r) * 32 + k4];
            xa[r] = pack2(xv.x, xv.y);
            xb[r] = pack2(xv.z, xv.w);
        }
#pragma unroll
        for (int c = 0; c < 4; c++) {
            float4 wv = Ws[k4 * WS_PITCH + c * 32 + lane];
            unsigned long long wa = pack2(wv.x, wv.y);
            unsigned long long wb = pack2(wv.z, wv.w);
#pragma unroll
            for (int r = 0; r < 8; r++) {
                fma2(acc2[r][c], xa[r], wa);
                fma2(acc2[r][c], xb[r], wb);
            }
        }
    }

    float bv[4], sv[4], biv[4];
#pragma unroll
    for (int c = 0; c < 4; c++) {
        bv[c]  = __ldg(b + c * 32 + lane);
        sv[c]  = __ldg(scale + c * 32 + lane);
        biv[c] = __ldg(bias + c * 32 + lane);
    }

#pragma unroll
    for (int r = 0; r < 8; r++) {
        int row = rowBase + r;
        if (row >= N_NODES) break;
        float v[4];
#pragma unroll
        for (int c = 0; c < 4; c++) {
            float2 p = unpack2(acc2[r][c]);
            v[c] = p.x + p.y + bv[c];
        }
        float s = v[0] + v[1] + v[2] + v[3];
#pragma unroll
        for (int o = 16; o; o >>= 1) s += __shfl_xor_sync(FULL, s, o);
        float mu = s * (1.0f / 128.0f);
        float q = 0.f;
#pragma unroll
        for (int c = 0; c < 4; c++) {
            float d = v[c] - mu;
            q += d * d;
        }
#pragma unroll
        for (int o = 16; o; o >>= 1) q += __shfl_xor_sync(FULL, q, o);
        float rstd = rsqrtf(q * (1.0f / 128.0f) + 1e-5f);
        size_t base = (size_t)row * DIM;
#pragma unroll
        for (int c = 0; c < 4; c++) {
            h_out[base + c * 32 + lane] = v[c];
            float t = fmaf((v[c] - mu) * rstd, sv[c], biv[c]);
            t_out[base + c * 32 + lane] = fmaxf(t, 0.0f);
        }
    }
}

// ---- CSR aggregation: acc[dst] = sum_e w * t[src]; optional fused LN ------
template <bool FUSE_LN>
__global__ void agg_kernel(const float* __restrict__ t,
                           const float* __restrict__ hres,
                           const float* __restrict__ scale,
                           const float* __restrict__ bias,
                           float* __restrict__ out) {
    int warp = threadIdx.x >> 5;
    int lane = threadIdx.x & 31;
    int row = blockIdx.x * 8 + warp;
    if (row >= N_NODES) return;

    int beg = g_off[row], end = g_off[row + 1];
    float4 acc = make_float4(0.f, 0.f, 0.f, 0.f);
    for (int i = beg; i < end; i++) {
        int s = g_cs[i];
        float w = g_cw[i];
        float4 v = ((const float4*)(t + (size_t)s * DIM))[lane];
        acc.x = fmaf(w, v.x, acc.x);
        acc.y = fmaf(w, v.y, acc.y);
        acc.z = fmaf(w, v.z, acc.z);
        acc.w = fmaf(w, v.w, acc.w);
    }

    size_t base = (size_t)row * DIM;
    if (FUSE_LN) {
        float4 o = ((const float4*)(hres + base))[lane];
        acc.x += o.x; acc.y += o.y; acc.z += o.z; acc.w += o.w;
        float s = acc.x + acc.y + acc.z + acc.w;
#pragma unroll
        for (int o2 = 16; o2; o2 >>= 1) s += __shfl_xor_sync(FULL, s, o2);
        float mu = s * (1.0f / 128.0f);
        float dx = acc.x - mu, dy = acc.y - mu, dz = acc.z - mu, dw = acc.w - mu;
        float q = dx * dx + dy * dy + dz * dz + dw * dw;
#pragma unroll
        for (int o2 = 16; o2; o2 >>= 1) q += __shfl_xor_sync(FULL, q, o2);
        float rstd = rsqrtf(q * (1.0f / 128.0f) + 1e-5f);
        float4 sc = ((const float4*)scale)[lane];
        float4 bi = ((const float4*)bias)[lane];
        float4 r;
        r.x = fmaxf(fmaf(dx * rstd, sc.x, bi.x), 0.0f);
        r.y = fmaxf(fmaf(dy * rstd, sc.y, bi.y), 0.0f);
        r.z = fmaxf(fmaf(dz * rstd, sc.z, bi.z), 0.0f);
        r.w = fmaxf(fmaf(dw * rstd, sc.w, bi.w), 0.0f);
        ((float4*)(out + base))[lane] = r;
    } else {
        ((float4*)(out + base))[lane] = acc;
    }
}

extern "C" void kernel_launch(void* const* d_in, const int* in_sizes, int n_in,
                              void* d_out, int out_size) {
    const float* x = nullptr;
    const int*   ei_raw = nullptr;
    const float* ef = nullptr;
    const float* lin_w = nullptr;
    const float* lin_b = nullptr;
    const float* ln_scale = nullptr;
    const float* ln_bias = nullptr;
    for (int i = 0; i < n_in; i++) {
        switch (in_sizes[i]) {
            case N_NODES * DIM: x      = (const float*)d_in[i]; break;
            case 2 * E_EDGES:   ei_raw = (const int*)d_in[i];   break;
            case E_EDGES:       ef     = (const float*)d_in[i]; break;
            case DIM * DIM:     lin_w  = (const float*)d_in[i]; break;
            case DIM:           lin_b  = (const float*)d_in[i]; break;
            case 2 * DIM:
                if (!ln_scale) ln_scale = (const float*)d_in[i];
                else           ln_bias  = (const float*)d_in[i];
                break;
            default: break;
        }
    }
    float* out = (float*)d_out;

    float *h, *t, *t2;
    cudaGetSymbolAddress((void**)&h,  g_h);
    cudaGetSymbolAddress((void**)&t,  g_t);
    cudaGetSymbolAddress((void**)&t2, g_t2);

    const int EDGE_BLKS = (E_EDGES + 255) / 256;
    const int NODE_BLKS = (N_NODES + 255) / 256;
    const int ROWS_GRID = (N_NODES + 7) / 8;
    const int GEMM_GRID = (N_NODES + 63) / 64;
    const int GEMM_SMEM = (32 * WS_PITCH + 8 * 8 * 32) * sizeof(float4);

    static bool attr_done = false;
    if (!attr_done) {
        cudaFuncSetAttribute(gemm_ln_kernel,
                             cudaFuncAttributeMaxDynamicSharedMemorySize,
                             GEMM_SMEM);
        attr_done = true;
    }

    // ---- CSR build (per call; deterministic) ----
    detect_kernel<<<1, 1>>>(ei_raw);
    zero_deg_kernel<<<NODE_BLKS, 256>>>();
    convert_hist_kernel<<<EDGE_BLKS, 256>>>(ei_raw);
    block_sum_kernel<<<SCAN_BLOCKS, 1024>>>();
    bsum_scan_kernel<<<1, 128>>>();
    scan_apply_kernel<<<SCAN_BLOCKS, 1024>>>();
    fill_kernel<<<EDGE_BLKS, 256>>>(ef);

    // ---- h = x@W^T+b ; t = relu(ln0(h)) ----
    gemm_ln_kernel<<<GEMM_GRID, 256, GEMM_SMEM>>>(x, lin_w, lin_b,
                                                  ln_scale, ln_bias, h, t);

    // ---- layer 0 agg + residual + LN1 + ReLU -> t2 ----
    agg_kernel<true><<<ROWS_GRID, 256>>>(t, h, ln_scale + DIM, ln_bias + DIM, t2);

    // ---- layer 1 agg -> out ----
    agg_kernel<false><<<ROWS_GRID, 256>>>(t2, nullptr, nullptr, nullptr, out);
}

// round 5
// speedup vs baseline: 11.4172x; 1.0464x over previous
#include <cuda_runtime.h>
#include <cuda_fp16.h>
#include <cstdint>

#define N_NODES 100000
#define E_EDGES 1600000
#define DIM 128
#define FULL 0xffffffffu
#define SCAN_BLOCKS 98   // 98 * 1024 >= N_NODES

// ------------------------- device scratch (no allocs) ----------------------
__device__ float  g_h[(size_t)N_NODES * DIM];    // ori = x@W^T + b (fp32)
__device__ __half g_t[(size_t)N_NODES * DIM];    // relu(ln0(h)), fp16
__device__ __half g_t2[(size_t)N_NODES * DIM];   // relu(ln1(agg0+h)), fp16
__device__ int    g_cs[E_EDGES];                 // CSR: src sorted by dst
__device__ float  g_cw[E_EDGES];                 // CSR: weight sorted by dst
__device__ int    g_deg[N_NODES];
__device__ int    g_off[N_NODES + 1];
__device__ int    g_cursor[N_NODES];
__device__ int    g_bsum[128];
__device__ int    g_boff[128];
__device__ int    g_is64;

// ---- f32x2 packed helpers (sm_103a FFMA2 path) ----------------------------
__device__ __forceinline__ unsigned long long pack2(float a, float b) {
    unsigned long long r;
    asm("mov.b64 %0, {%1, %2};" : "=l"(r) : "f"(a), "f"(b));
    return r;
}
__device__ __forceinline__ void fma2(unsigned long long& d,
                                     unsigned long long a,
                                     unsigned long long b) {
    asm("fma.rn.f32x2 %0, %1, %2, %0;" : "+l"(d) : "l"(a), "l"(b));
}
__device__ __forceinline__ float2 unpack2(unsigned long long v) {
    float2 r;
    asm("mov.b64 {%0, %1}, %2;" : "=f"(r.x), "=f"(r.y) : "l"(v));
    return r;
}

// ---- detect int64 vs int32 edge layout: one warp, ballot ------------------
__global__ void detect_kernel(const int* __restrict__ raw) {
    int lane = threadIdx.x;
    int nz = 0;
    // check hi words of first 64 int64 entries (2 per lane)
    if (raw[2 * (2 * lane + 0) + 1] != 0) nz = 1;
    if (raw[2 * (2 * lane + 1) + 1] != 0) nz = 1;
    unsigned m = __ballot_sync(FULL, nz);
    if (lane == 0) g_is64 = (m == 0u) ? 1 : 0;
}

__global__ void zero_deg_kernel() {
    int i = blockIdx.x * blockDim.x + threadIdx.x;
    if (i < N_NODES) g_deg[i] = 0;
}

// ---- histogram dst degrees (reads raw directly) ---------------------------
__global__ void hist_kernel(const int* __restrict__ raw) {
    int e = blockIdx.x * blockDim.x + threadIdx.x;
    if (e >= E_EDGES) return;
    int d = g_is64 ? raw[2 * ((size_t)E_EDGES + e)] : raw[E_EDGES + e];
    d = min(max(d, 0), N_NODES - 1);
    atomicAdd(&g_deg[d], 1);
}

// ---- parallel scan, phase 1: per-block sums -------------------------------
__global__ void block_sum_kernel() {
    __shared__ int ws[32];
    int tid = threadIdx.x, lane = tid & 31, wid = tid >> 5;
    int idx = blockIdx.x * 1024 + tid;
    int v = (idx < N_NODES) ? g_deg[idx] : 0;
#pragma unroll
    for (int o = 16; o; o >>= 1) v += __shfl_xor_sync(FULL, v, o);
    if (lane == 0) ws[wid] = v;
    __syncthreads();
    if (wid == 0) {
        int s = ws[lane];
#pragma unroll
        for (int o = 16; o; o >>= 1) s += __shfl_xor_sync(FULL, s, o);
        if (lane == 0) g_bsum[blockIdx.x] = s;
    }
}

// ---- parallel scan, phase 2: exclusive scan of block sums (1 block) -------
__global__ void bsum_scan_kernel() {
    __shared__ int s[128];
    int tid = threadIdx.x;
    int v = (tid < SCAN_BLOCKS) ? g_bsum[tid] : 0;
    s[tid] = v;
    __syncthreads();
#pragma unroll
    for (int o = 1; o < 128; o <<= 1) {
        int t = (tid >= o) ? s[tid - o] : 0;
        __syncthreads();
        s[tid] += t;
        __syncthreads();
    }
    g_boff[tid] = s[tid] - v;   // exclusive
}

// ---- parallel scan, phase 3: block-local scan + base ----------------------
__global__ void scan_apply_kernel() {
    __shared__ int wsum[32];
    int tid = threadIdx.x, lane = tid & 31, wid = tid >> 5;
    int idx = blockIdx.x * 1024 + tid;
    int v = (idx < N_NODES) ? g_deg[idx] : 0;
    int inc = v;
#pragma unroll
    for (int o = 1; o < 32; o <<= 1) {
        int n = __shfl_up_sync(FULL, inc, o);
        if (lane >= o) inc += n;
    }
    if (lane == 31) wsum[wid] = inc;
    __syncthreads();
    if (wid == 0) {
        int w = wsum[lane];
        int wi = w;
#pragma unroll
        for (int o = 1; o < 32; o <<= 1) {
            int n = __shfl_up_sync(FULL, wi, o);
            if (lane >= o) wi += n;
        }
        wsum[lane] = wi - w;
    }
    __syncthreads();
    int excl = g_boff[blockIdx.x] + wsum[wid] + (inc - v);
    if (idx < N_NODES) { g_off[idx] = excl; g_cursor[idx] = excl; }
    if (idx == 0) g_off[N_NODES] = E_EDGES;
}

// ---- fill CSR buckets (re-reads raw) --------------------------------------
__global__ void fill_kernel(const int* __restrict__ raw,
                            const float* __restrict__ ef) {
    int e = blockIdx.x * blockDim.x + threadIdx.x;
    if (e >= E_EDGES) return;
    int s, d;
    if (g_is64) {
        s = raw[2 * (size_t)e];
        d = raw[2 * ((size_t)E_EDGES + e)];
    } else {
        s = raw[e];
        d = raw[E_EDGES + e];
    }
    s = min(max(s, 0), N_NODES - 1);
    d = min(max(d, 0), N_NODES - 1);
    int pos = atomicAdd(&g_cursor[d], 1);
    g_cs[pos] = s;
    g_cw[pos] = ef[e];
}

// ---- GEMM (h = x @ W^T + b) fused with LN0 + ReLU, f32x2 FMA --------------
#define WS_PITCH 132
__global__ void gemm_ln_kernel(const float* __restrict__ x,
                               const float* __restrict__ W,
                               const float* __restrict__ b,
                               const float* __restrict__ scale,
                               const float* __restrict__ bias,
                               float* __restrict__ h_out,
                               __half* __restrict__ t_out) {
    extern __shared__ float4 smem[];
    float4* Ws = smem;                      // [k4][col] pitch WS_PITCH
    float4* Xs = smem + 32 * WS_PITCH;      // [warp*8 + r][k4]

    int tid = threadIdx.x, lane = tid & 31, warp = tid >> 5;
    int rowBase = blockIdx.x * 64 + warp * 8;

    for (int idx = tid; idx < DIM * 32; idx += 256) {
        int col = idx >> 5, k4 = idx & 31;
        Ws[k4 * WS_PITCH + col] = ((const float4*)W)[idx];
    }
    for (int r = 0; r < 8; r++) {
        int row = rowBase + r;
        float4 v = make_float4(0.f, 0.f, 0.f, 0.f);
        if (row < N_NODES) v = ((const float4*)x)[(size_t)row * 32 + lane];
        Xs[(warp * 8 + r) * 32 + lane] = v;
    }
    __syncthreads();

    unsigned long long acc2[8][4];
#pragma unroll
    for (int r = 0; r < 8; r++)
#pragma unroll
        for (int c = 0; c < 4; c++) acc2[r][c] = 0ull;

    for (int k4 = 0; k4 < 32; k4++) {
        unsigned long long xa[8], xb[8];
#pragma unroll
        for (int r = 0; r < 8; r++) {
            float4 xv = Xs[(warp * 8 + r) * 32 + k4];
            xa[r] = pack2(xv.x, xv.y);
            xb[r] = pack2(xv.z, xv.w);
        }
#pragma unroll
        for (int c = 0; c < 4; c++) {
            float4 wv = Ws[k4 * WS_PITCH + c * 32 + lane];
            unsigned long long wa = pack2(wv.x, wv.y);
            unsigned long long wb = pack2(wv.z, wv.w);
#pragma unroll
            for (int r = 0; r < 8; r++) {
                fma2(acc2[r][c], xa[r], wa);
                fma2(acc2[r][c], xb[r], wb);
            }
        }
    }

    float bv[4], sv[4], biv[4];
#pragma unroll
    for (int c = 0; c < 4; c++) {
        bv[c]  = __ldg(b + c * 32 + lane);
        sv[c]  = __ldg(scale + c * 32 + lane);
        biv[c] = __ldg(bias + c * 32 + lane);
    }

#pragma unroll
    for (int r = 0; r < 8; r++) {
        int row = rowBase + r;
        if (row >= N_NODES) break;
        float v[4];
#pragma unroll
        for (int c = 0; c < 4; c++) {
            float2 p = unpack2(acc2[r][c]);
            v[c] = p.x + p.y + bv[c];
        }
        float s = v[0] + v[1] + v[2] + v[3];
#pragma unroll
        for (int o = 16; o; o >>= 1) s += __shfl_xor_sync(FULL, s, o);
        float mu = s * (1.0f / 128.0f);
        float q = 0.f;
#pragma unroll
        for (int c = 0; c < 4; c++) {
            float d = v[c] - mu;
            q += d * d;
        }
#pragma unroll
        for (int o = 16; o; o >>= 1) q += __shfl_xor_sync(FULL, q, o);
        float rstd = rsqrtf(q * (1.0f / 128.0f) + 1e-5f);
        size_t base = (size_t)row * DIM;
#pragma unroll
        for (int c = 0; c < 4; c++) {
            h_out[base + c * 32 + lane] = v[c];
            float t = fmaf((v[c] - mu) * rstd, sv[c], biv[c]);
            t_out[base + c * 32 + lane] = __float2half_rn(fmaxf(t, 0.0f));
        }
    }
}

// ---- CSR aggregation from fp16 activations --------------------------------
// FUSE_LN=true: out is __half* (t2);  false: out is float* (final output).
template <bool FUSE_LN>
__global__ void agg_kernel(const __half* __restrict__ t,
                           const float* __restrict__ hres,
                           const float* __restrict__ scale,
                           const float* __restrict__ bias,
                           void* __restrict__ outp) {
    int warp = threadIdx.x >> 5;
    int lane = threadIdx.x & 31;
    int row = blockIdx.x * 8 + warp;
    if (row >= N_NODES) return;

    int beg = g_off[row], end = g_off[row + 1];
    float4 acc = make_float4(0.f, 0.f, 0.f, 0.f);
#pragma unroll 2
    for (int i = beg; i < end; i++) {
        int s = g_cs[i];                 // warp-uniform
        float w = g_cw[i];               // warp-uniform
        uint2 rv = ((const uint2*)(t + (size_t)s * DIM))[lane];
        float2 f0 = __half22float2(*(const __half2*)&rv.x);
        float2 f1 = __half22float2(*(const __half2*)&rv.y);
        acc.x = fmaf(w, f0.x, acc.x);
        acc.y = fmaf(w, f0.y, acc.y);
        acc.z = fmaf(w, f1.x, acc.z);
        acc.w = fmaf(w, f1.y, acc.w);
    }

    size_t base = (size_t)row * DIM;
    if (FUSE_LN) {
        float4 o = ((const float4*)(hres + base))[lane];
        acc.x += o.x; acc.y += o.y; acc.z += o.z; acc.w += o.w;
        float s = acc.x + acc.y + acc.z + acc.w;
#pragma unroll
        for (int o2 = 16; o2; o2 >>= 1) s += __shfl_xor_sync(FULL, s, o2);
        float mu = s * (1.0f / 128.0f);
        float dx = acc.x - mu, dy = acc.y - mu, dz = acc.z - mu, dw = acc.w - mu;
        float q = dx * dx + dy * dy + dz * dz + dw * dw;
#pragma unroll
        for (int o2 = 16; o2; o2 >>= 1) q += __shfl_xor_sync(FULL, q, o2);
        float rstd = rsqrtf(q * (1.0f / 128.0f) + 1e-5f);
        float4 sc = ((const float4*)scale)[lane];
        float4 bi = ((const float4*)bias)[lane];
        float rx = fmaxf(fmaf(dx * rstd, sc.x, bi.x), 0.0f);
        float ry = fmaxf(fmaf(dy * rstd, sc.y, bi.y), 0.0f);
        float rz = fmaxf(fmaf(dz * rstd, sc.z, bi.z), 0.0f);
        float rw = fmaxf(fmaf(dw * rstd, sc.w, bi.w), 0.0f);
        uint2 st;
        *(__half2*)&st.x = __floats2half2_rn(rx, ry);
        *(__half2*)&st.y = __floats2half2_rn(rz, rw);
        ((uint2*)((__half*)outp + base))[lane] = st;
    } else {
        ((float4*)((float*)outp + base))[lane] = acc;
    }
}

extern "C" void kernel_launch(void* const* d_in, const int* in_sizes, int n_in,
                              void* d_out, int out_size) {
    const float* x = nullptr;
    const int*   ei_raw = nullptr;
    const float* ef = nullptr;
    const float* lin_w = nullptr;
    const float* lin_b = nullptr;
    const float* ln_scale = nullptr;
    const float* ln_bias = nullptr;
    for (int i = 0; i < n_in; i++) {
        switch (in_sizes[i]) {
            case N_NODES * DIM: x      = (const float*)d_in[i]; break;
            case 2 * E_EDGES:   ei_raw = (const int*)d_in[i];   break;
            case E_EDGES:       ef     = (const float*)d_in[i]; break;
            case DIM * DIM:     lin_w  = (const float*)d_in[i]; break;
            case DIM:           lin_b  = (const float*)d_in[i]; break;
            case 2 * DIM:
                if (!ln_scale) ln_scale = (const float*)d_in[i];
                else           ln_bias  = (const float*)d_in[i];
                break;
            default: break;
        }
    }
    float* out = (float*)d_out;

    float  *h;
    __half *t, *t2;
    cudaGetSymbolAddress((void**)&h,  g_h);
    cudaGetSymbolAddress((void**)&t,  g_t);
    cudaGetSymbolAddress((void**)&t2, g_t2);

    const int EDGE_BLKS = (E_EDGES + 255) / 256;
    const int NODE_BLKS = (N_NODES + 255) / 256;
    const int ROWS_GRID = (N_NODES + 7) / 8;
    const int GEMM_GRID = (N_NODES + 63) / 64;
    const int GEMM_SMEM = (32 * WS_PITCH + 8 * 8 * 32) * sizeof(float4);

    static bool attr_done = false;
    if (!attr_done) {
        cudaFuncSetAttribute(gemm_ln_kernel,
                             cudaFuncAttributeMaxDynamicSharedMemorySize,
                             GEMM_SMEM);
        attr_done = true;
    }

    // ---- CSR build ----
    detect_kernel<<<1, 32>>>(ei_raw);
    zero_deg_kernel<<<NODE_BLKS, 256>>>();
    hist_kernel<<<EDGE_BLKS, 256>>>(ei_raw);
    block_sum_kernel<<<SCAN_BLOCKS, 1024>>>();
    bsum_scan_kernel<<<1, 128>>>();
    scan_apply_kernel<<<SCAN_BLOCKS, 1024>>>();
    fill_kernel<<<EDGE_BLKS, 256>>>(ei_raw, ef);

    // ---- h = x@W^T+b ; t = relu(ln0(h)) in fp16 ----
    gemm_ln_kernel<<<GEMM_GRID, 256, GEMM_SMEM>>>(x, lin_w, lin_b,
                                                  ln_scale, ln_bias, h, t);

    // ---- layer 0 agg + residual + LN1 + ReLU -> t2 (fp16) ----
    agg_kernel<true><<<ROWS_GRID, 256>>>(t, h, ln_scale + DIM, ln_bias + DIM,
                                         (void*)t2);

    // ---- layer 1 agg -> out (fp32) ----
    agg_kernel<false><<<ROWS_GRID, 256>>>(t2, nullptr, nullptr, nullptr,
                                          (void*)out);
}

// round 6
// speedup vs baseline: 12.7379x; 1.1157x over previous
#include <cuda_runtime.h>
#include <cuda_fp16.h>
#include <cstdint>

#define N_NODES 100000
#define E_EDGES 1600000
#define DIM 128
#define FULL 0xffffffffu
#define SCAN_BLOCKS 98   // 98 * 1024 >= N_NODES

// ------------------------- device scratch (no allocs) ----------------------
__device__ float  g_h[(size_t)N_NODES * DIM];    // ori = x@W^T + b (fp32)
__device__ __half g_t[(size_t)N_NODES * DIM];    // relu(ln0(h)), fp16
__device__ __half g_t2[(size_t)N_NODES * DIM];   // relu(ln1(agg0+h)), fp16
__device__ int    g_cs[E_EDGES];                 // CSR: src sorted by dst
__device__ float  g_cw[E_EDGES];                 // CSR: weight sorted by dst
__device__ int    g_deg[N_NODES];
__device__ int    g_off[N_NODES + 1];
__device__ int    g_cursor[N_NODES];
__device__ int    g_bsum[128];
__device__ int    g_boff[128];
__device__ int    g_is64;

// ---- f32x2 packed helpers (sm_103a FFMA2 path) ----------------------------
__device__ __forceinline__ unsigned long long pack2(float a, float b) {
    unsigned long long r;
    asm("mov.b64 %0, {%1, %2};" : "=l"(r) : "f"(a), "f"(b));
    return r;
}
__device__ __forceinline__ void fma2(unsigned long long& d,
                                     unsigned long long a,
                                     unsigned long long b) {
    asm("fma.rn.f32x2 %0, %1, %2, %0;" : "+l"(d) : "l"(a), "l"(b));
}
__device__ __forceinline__ float2 unpack2(unsigned long long v) {
    float2 r;
    asm("mov.b64 {%0, %1}, %2;" : "=f"(r.x), "=f"(r.y) : "l"(v));
    return r;
}

// ---- detect int64 vs int32 edge layout: one warp, ballot ------------------
__global__ void detect_kernel(const int* __restrict__ raw) {
    int lane = threadIdx.x;
    int nz = 0;
    if (raw[2 * (2 * lane + 0) + 1] != 0) nz = 1;
    if (raw[2 * (2 * lane + 1) + 1] != 0) nz = 1;
    unsigned m = __ballot_sync(FULL, nz);
    if (lane == 0) g_is64 = (m == 0u) ? 1 : 0;
}

__global__ void zero_deg_kernel() {
    int i = blockIdx.x * blockDim.x + threadIdx.x;
    if (i < N_NODES) g_deg[i] = 0;
}

// ---- histogram dst degrees ------------------------------------------------
__global__ void hist_kernel(const int* __restrict__ raw) {
    int e = blockIdx.x * blockDim.x + threadIdx.x;
    if (e >= E_EDGES) return;
    int d = g_is64 ? raw[2 * ((size_t)E_EDGES + e)] : raw[E_EDGES + e];
    d = min(max(d, 0), N_NODES - 1);
    atomicAdd(&g_deg[d], 1);
}

// ---- parallel scan, phase 1: per-block sums -------------------------------
__global__ void block_sum_kernel() {
    __shared__ int ws[32];
    int tid = threadIdx.x, lane = tid & 31, wid = tid >> 5;
    int idx = blockIdx.x * 1024 + tid;
    int v = (idx < N_NODES) ? g_deg[idx] : 0;
#pragma unroll
    for (int o = 16; o; o >>= 1) v += __shfl_xor_sync(FULL, v, o);
    if (lane == 0) ws[wid] = v;
    __syncthreads();
    if (wid == 0) {
        int s = ws[lane];
#pragma unroll
        for (int o = 16; o; o >>= 1) s += __shfl_xor_sync(FULL, s, o);
        if (lane == 0) g_bsum[blockIdx.x] = s;
    }
}

// ---- parallel scan, phase 2: exclusive scan of block sums -----------------
__global__ void bsum_scan_kernel() {
    __shared__ int s[128];
    int tid = threadIdx.x;
    int v = (tid < SCAN_BLOCKS) ? g_bsum[tid] : 0;
    s[tid] = v;
    __syncthreads();
#pragma unroll
    for (int o = 1; o < 128; o <<= 1) {
        int t = (tid >= o) ? s[tid - o] : 0;
        __syncthreads();
        s[tid] += t;
        __syncthreads();
    }
    g_boff[tid] = s[tid] - v;   // exclusive
}

// ---- parallel scan, phase 3: block-local scan + base ----------------------
__global__ void scan_apply_kernel() {
    __shared__ int wsum[32];
    int tid = threadIdx.x, lane = tid & 31, wid = tid >> 5;
    int idx = blockIdx.x * 1024 + tid;
    int v = (idx < N_NODES) ? g_deg[idx] : 0;
    int inc = v;
#pragma unroll
    for (int o = 1; o < 32; o <<= 1) {
        int n = __shfl_up_sync(FULL, inc, o);
        if (lane >= o) inc += n;
    }
    if (lane == 31) wsum[wid] = inc;
    __syncthreads();
    if (wid == 0) {
        int w = wsum[lane];
        int wi = w;
#pragma unroll
        for (int o = 1; o < 32; o <<= 1) {
            int n = __shfl_up_sync(FULL, wi, o);
            if (lane >= o) wi += n;
        }
        wsum[lane] = wi - w;
    }
    __syncthreads();
    int excl = g_boff[blockIdx.x] + wsum[wid] + (inc - v);
    if (idx < N_NODES) { g_off[idx] = excl; g_cursor[idx] = excl; }
    if (idx == 0) g_off[N_NODES] = E_EDGES;
}

// ---- fill CSR buckets -----------------------------------------------------
__global__ void fill_kernel(const int* __restrict__ raw,
                            const float* __restrict__ ef) {
    int e = blockIdx.x * blockDim.x + threadIdx.x;
    if (e >= E_EDGES) return;
    int s, d;
    if (g_is64) {
        s = raw[2 * (size_t)e];
        d = raw[2 * ((size_t)E_EDGES + e)];
    } else {
        s = raw[e];
        d = raw[E_EDGES + e];
    }
    s = min(max(s, 0), N_NODES - 1);
    d = min(max(d, 0), N_NODES - 1);
    int pos = atomicAdd(&g_cursor[d], 1);
    g_cs[pos] = s;
    g_cw[pos] = ef[e];
}

// ---- GEMM (h = x @ W^T + b) fused with LN0 + ReLU, f32x2 FMA --------------
#define WS_PITCH 132
__global__ void gemm_ln_kernel(const float* __restrict__ x,
                               const float* __restrict__ W,
                               const float* __restrict__ b,
                               const float* __restrict__ scale,
                               const float* __restrict__ bias,
                               float* __restrict__ h_out,
                               __half* __restrict__ t_out) {
    extern __shared__ float4 smem[];
    float4* Ws = smem;                      // [k4][col] pitch WS_PITCH
    float4* Xs = smem + 32 * WS_PITCH;      // [warp*8 + r][k4]

    int tid = threadIdx.x, lane = tid & 31, warp = tid >> 5;
    int rowBase = blockIdx.x * 64 + warp * 8;

    for (int idx = tid; idx < DIM * 32; idx += 256) {
        int col = idx >> 5, k4 = idx & 31;
        Ws[k4 * WS_PITCH + col] = ((const float4*)W)[idx];
    }
    for (int r = 0; r < 8; r++) {
        int row = rowBase + r;
        float4 v = make_float4(0.f, 0.f, 0.f, 0.f);
        if (row < N_NODES) v = ((const float4*)x)[(size_t)row * 32 + lane];
        Xs[(warp * 8 + r) * 32 + lane] = v;
    }
    __syncthreads();

    unsigned long long acc2[8][4];
#pragma unroll
    for (int r = 0; r < 8; r++)
#pragma unroll
        for (int c = 0; c < 4; c++) acc2[r][c] = 0ull;

    for (int k4 = 0; k4 < 32; k4++) {
        unsigned long long xa[8], xb[8];
#pragma unroll
        for (int r = 0; r < 8; r++) {
            float4 xv = Xs[(warp * 8 + r) * 32 + k4];
            xa[r] = pack2(xv.x, xv.y);
            xb[r] = pack2(xv.z, xv.w);
        }
#pragma unroll
        for (int c = 0; c < 4; c++) {
            float4 wv = Ws[k4 * WS_PITCH + c * 32 + lane];
            unsigned long long wa = pack2(wv.x, wv.y);
            unsigned long long wb = pack2(wv.z, wv.w);
#pragma unroll
            for (int r = 0; r < 8; r++) {
                fma2(acc2[r][c], xa[r], wa);
                fma2(acc2[r][c], xb[r], wb);
            }
        }
    }

    float bv[4], sv[4], biv[4];
#pragma unroll
    for (int c = 0; c < 4; c++) {
        bv[c]  = __ldg(b + c * 32 + lane);
        sv[c]  = __ldg(scale + c * 32 + lane);
        biv[c] = __ldg(bias + c * 32 + lane);
    }

#pragma unroll
    for (int r = 0; r < 8; r++) {
        int row = rowBase + r;
        if (row >= N_NODES) break;
        float v[4];
#pragma unroll
        for (int c = 0; c < 4; c++) {
            float2 p = unpack2(acc2[r][c]);
            v[c] = p.x + p.y + bv[c];
        }
        float s = v[0] + v[1] + v[2] + v[3];
#pragma unroll
        for (int o = 16; o; o >>= 1) s += __shfl_xor_sync(FULL, s, o);
        float mu = s * (1.0f / 128.0f);
        float q = 0.f;
#pragma unroll
        for (int c = 0; c < 4; c++) {
            float d = v[c] - mu;
            q += d * d;
        }
#pragma unroll
        for (int o = 16; o; o >>= 1) q += __shfl_xor_sync(FULL, q, o);
        float rstd = rsqrtf(q * (1.0f / 128.0f) + 1e-5f);
        size_t base = (size_t)row * DIM;
#pragma unroll
        for (int c = 0; c < 4; c++) {
            h_out[base + c * 32 + lane] = v[c];
            float t = fmaf((v[c] - mu) * rstd, sv[c], biv[c]);
            t_out[base + c * 32 + lane] = __float2half_rn(fmaxf(t, 0.0f));
        }
    }
}

// ---- CSR aggregation, MLP-8 chunked gathers -------------------------------
// FUSE_LN=true: out is __half* (t2);  false: out is float* (final output).
#define CHUNK 8
template <bool FUSE_LN>
__global__ void agg_kernel(const __half* __restrict__ t,
                           const float* __restrict__ hres,
                           const float* __restrict__ scale,
                           const float* __restrict__ bias,
                           void* __restrict__ outp) {
    int warp = threadIdx.x >> 5;
    int lane = threadIdx.x & 31;
    int row = blockIdx.x * 8 + warp;
    if (row >= N_NODES) return;

    int beg = g_off[row], end = g_off[row + 1];
    float4 acc = make_float4(0.f, 0.f, 0.f, 0.f);

    int i = beg;
    // main chunks: batch 8 independent gathers -> MLP 8
    for (; i + CHUNK <= end; i += CHUNK) {
        int   sI[CHUNK];
        float wI[CHUNK];
#pragma unroll
        for (int j = 0; j < CHUNK; j++) {
            sI[j] = __ldg(g_cs + i + j);       // warp-uniform
            wI[j] = __ldg(g_cw + i + j);
        }
        uint2 rv[CHUNK];
#pragma unroll
        for (int j = 0; j < CHUNK; j++)
            rv[j] = ((const uint2*)(t + (size_t)sI[j] * DIM))[lane];
#pragma unroll
        for (int j = 0; j < CHUNK; j++) {
            float2 f0 = __half22float2(*(const __half2*)&rv[j].x);
            float2 f1 = __half22float2(*(const __half2*)&rv[j].y);
            acc.x = fmaf(wI[j], f0.x, acc.x);
            acc.y = fmaf(wI[j], f0.y, acc.y);
            acc.z = fmaf(wI[j], f1.x, acc.z);
            acc.w = fmaf(wI[j], f1.y, acc.w);
        }
    }
    // tail
    for (; i < end; i++) {
        int s = __ldg(g_cs + i);
        float w = __ldg(g_cw + i);
        uint2 rv = ((const uint2*)(t + (size_t)s * DIM))[lane];
        float2 f0 = __half22float2(*(const __half2*)&rv.x);
        float2 f1 = __half22float2(*(const __half2*)&rv.y);
        acc.x = fmaf(w, f0.x, acc.x);
        acc.y = fmaf(w, f0.y, acc.y);
        acc.z = fmaf(w, f1.x, acc.z);
        acc.w = fmaf(w, f1.y, acc.w);
    }

    size_t base = (size_t)row * DIM;
    if (FUSE_LN) {
        float4 o = ((const float4*)(hres + base))[lane];
        acc.x += o.x; acc.y += o.y; acc.z += o.z; acc.w += o.w;
        float s = acc.x + acc.y + acc.z + acc.w;
#pragma unroll
        for (int o2 = 16; o2; o2 >>= 1) s += __shfl_xor_sync(FULL, s, o2);
        float mu = s * (1.0f / 128.0f);
        float dx = acc.x - mu, dy = acc.y - mu, dz = acc.z - mu, dw = acc.w - mu;
        float q = dx * dx + dy * dy + dz * dz + dw * dw;
#pragma unroll
        for (int o2 = 16; o2; o2 >>= 1) q += __shfl_xor_sync(FULL, q, o2);
        float rstd = rsqrtf(q * (1.0f / 128.0f) + 1e-5f);
        float4 sc = ((const float4*)scale)[lane];
        float4 bi = ((const float4*)bias)[lane];
        float rx = fmaxf(fmaf(dx * rstd, sc.x, bi.x), 0.0f);
        float ry = fmaxf(fmaf(dy * rstd, sc.y, bi.y), 0.0f);
        float rz = fmaxf(fmaf(dz * rstd, sc.z, bi.z), 0.0f);
        float rw = fmaxf(fmaf(dw * rstd, sc.w, bi.w), 0.0f);
        uint2 st;
        *(__half2*)&st.x = __floats2half2_rn(rx, ry);
        *(__half2*)&st.y = __floats2half2_rn(rz, rw);
        ((uint2*)((__half*)outp + base))[lane] = st;
    } else {
        ((float4*)((float*)outp + base))[lane] = acc;
    }
}

extern "C" void kernel_launch(void* const* d_in, const int* in_sizes, int n_in,
                              void* d_out, int out_size) {
    const float* x = nullptr;
    const int*   ei_raw = nullptr;
    const float* ef = nullptr;
    const float* lin_w = nullptr;
    const float* lin_b = nullptr;
    const float* ln_scale = nullptr;
    const float* ln_bias = nullptr;
    for (int i = 0; i < n_in; i++) {
        switch (in_sizes[i]) {
            case N_NODES * DIM: x      = (const float*)d_in[i]; break;
            case 2 * E_EDGES:   ei_raw = (const int*)d_in[i];   break;
            case E_EDGES:       ef     = (const float*)d_in[i]; break;
            case DIM * DIM:     lin_w  = (const float*)d_in[i]; break;
            case DIM:           lin_b  = (const float*)d_in[i]; break;
            case 2 * DIM:
                if (!ln_scale) ln_scale = (const float*)d_in[i];
                else           ln_bias  = (const float*)d_in[i];
                break;
            default: break;
        }
    }
    float* out = (float*)d_out;

    float  *h;
    __half *t, *t2;
    cudaGetSymbolAddress((void**)&h,  g_h);
    cudaGetSymbolAddress((void**)&t,  g_t);
    cudaGetSymbolAddress((void**)&t2, g_t2);

    const int EDGE_BLKS = (E_EDGES + 255) / 256;
    const int NODE_BLKS = (N_NODES + 255) / 256;
    const int ROWS_GRID = (N_NODES + 7) / 8;
    const int GEMM_GRID = (N_NODES + 63) / 64;
    const int GEMM_SMEM = (32 * WS_PITCH + 8 * 8 * 32) * sizeof(float4);

    static bool attr_done = false;
    if (!attr_done) {
        cudaFuncSetAttribute(gemm_ln_kernel,
                             cudaFuncAttributeMaxDynamicSharedMemorySize,
                             GEMM_SMEM);
        attr_done = true;
    }

    // ---- CSR build ----
    detect_kernel<<<1, 32>>>(ei_raw);
    zero_deg_kernel<<<NODE_BLKS, 256>>>();
    hist_kernel<<<EDGE_BLKS, 256>>>(ei_raw);
    block_sum_kernel<<<SCAN_BLOCKS, 1024>>>();
    bsum_scan_kernel<<<1, 128>>>();
    scan_apply_kernel<<<SCAN_BLOCKS, 1024>>>();
    fill_kernel<<<EDGE_BLKS, 256>>>(ei_raw, ef);

    // ---- h = x@W^T+b ; t = relu(ln0(h)) in fp16 ----
    gemm_ln_kernel<<<GEMM_GRID, 256, GEMM_SMEM>>>(x, lin_w, lin_b,
                                                  ln_scale, ln_bias, h, t);

    // ---- layer 0 agg + residual + LN1 + ReLU -> t2 (fp16) ----
    agg_kernel<true><<<ROWS_GRID, 256>>>(t, h, ln_scale + DIM, ln_bias + DIM,
                                         (void*)t2);

    // ---- layer 1 agg -> out (fp32) ----
    agg_kernel<false><<<ROWS_GRID, 256>>>(t2, nullptr, nullptr, nullptr,
                                          (void*)out);
}

// round 7
// speedup vs baseline: 13.6479x; 1.0714x over previous
#include <cuda_runtime.h>
#include <cuda_fp16.h>
#include <cstdint>

#define N_NODES 100000
#define E_EDGES 1600000
#define DIM 128
#define FULL 0xffffffffu
#define SCAN_BLOCKS 98   // 98 * 1024 >= N_NODES

// ------------------------- device scratch (no allocs) ----------------------
__device__ float  g_h[(size_t)N_NODES * DIM];    // ori = x@W^T + b (fp32)
__device__ __half g_t[(size_t)N_NODES * DIM];    // relu(ln0(h)), fp16
__device__ __half g_t2[(size_t)N_NODES * DIM];   // relu(ln1(agg0+h)), fp16
__device__ int2   g_edge[E_EDGES];               // CSR: (src, w-bits) by dst
__device__ int    g_deg[N_NODES];
__device__ int    g_off[N_NODES + 1];
__device__ int    g_cursor[N_NODES];
__device__ int    g_bsum[128];
__device__ int    g_boff[128];
__device__ int    g_is64;

// ---- f32x2 packed helpers (sm_103a FFMA2 path) ----------------------------
__device__ __forceinline__ unsigned long long pack2(float a, float b) {
    unsigned long long r;
    asm("mov.b64 %0, {%1, %2};" : "=l"(r) : "f"(a), "f"(b));
    return r;
}
__device__ __forceinline__ void fma2(unsigned long long& d,
                                     unsigned long long a,
                                     unsigned long long b) {
    asm("fma.rn.f32x2 %0, %1, %2, %0;" : "+l"(d) : "l"(a), "l"(b));
}
__device__ __forceinline__ float2 unpack2(unsigned long long v) {
    float2 r;
    asm("mov.b64 {%0, %1}, %2;" : "=f"(r.x), "=f"(r.y) : "l"(v));
    return r;
}

// ---- detect int64 vs int32 edge layout: one warp, ballot ------------------
__global__ void detect_kernel(const int* __restrict__ raw) {
    int lane = threadIdx.x;
    int nz = 0;
    if (raw[2 * (2 * lane + 0) + 1] != 0) nz = 1;
    if (raw[2 * (2 * lane + 1) + 1] != 0) nz = 1;
    unsigned m = __ballot_sync(FULL, nz);
    if (lane == 0) g_is64 = (m == 0u) ? 1 : 0;
}

__global__ void zero_deg_kernel() {
    int i = blockIdx.x * blockDim.x + threadIdx.x;
    if (i < N_NODES) g_deg[i] = 0;
}

// ---- histogram dst degrees ------------------------------------------------
__global__ void hist_kernel(const int* __restrict__ raw) {
    int e = blockIdx.x * blockDim.x + threadIdx.x;
    if (e >= E_EDGES) return;
    int d = g_is64 ? raw[2 * ((size_t)E_EDGES + e)] : raw[E_EDGES + e];
    d = min(max(d, 0), N_NODES - 1);
    atomicAdd(&g_deg[d], 1);
}

// ---- parallel scan, phase 1: per-block sums -------------------------------
__global__ void block_sum_kernel() {
    __shared__ int ws[32];
    int tid = threadIdx.x, lane = tid & 31, wid = tid >> 5;
    int idx = blockIdx.x * 1024 + tid;
    int v = (idx < N_NODES) ? g_deg[idx] : 0;
#pragma unroll
    for (int o = 16; o; o >>= 1) v += __shfl_xor_sync(FULL, v, o);
    if (lane == 0) ws[wid] = v;
    __syncthreads();
    if (wid == 0) {
        int s = ws[lane];
#pragma unroll
        for (int o = 16; o; o >>= 1) s += __shfl_xor_sync(FULL, s, o);
        if (lane == 0) g_bsum[blockIdx.x] = s;
    }
}

// ---- parallel scan, phase 2: exclusive scan of block sums -----------------
__global__ void bsum_scan_kernel() {
    __shared__ int s[128];
    int tid = threadIdx.x;
    int v = (tid < SCAN_BLOCKS) ? g_bsum[tid] : 0;
    s[tid] = v;
    __syncthreads();
#pragma unroll
    for (int o = 1; o < 128; o <<= 1) {
        int t = (tid >= o) ? s[tid - o] : 0;
        __syncthreads();
        s[tid] += t;
        __syncthreads();
    }
    g_boff[tid] = s[tid] - v;   // exclusive
}

// ---- parallel scan, phase 3: block-local scan + base ----------------------
__global__ void scan_apply_kernel() {
    __shared__ int wsum[32];
    int tid = threadIdx.x, lane = tid & 31, wid = tid >> 5;
    int idx = blockIdx.x * 1024 + tid;
    int v = (idx < N_NODES) ? g_deg[idx] : 0;
    int inc = v;
#pragma unroll
    for (int o = 1; o < 32; o <<= 1) {
        int n = __shfl_up_sync(FULL, inc, o);
        if (lane >= o) inc += n;
    }
    if (lane == 31) wsum[wid] = inc;
    __syncthreads();
    if (wid == 0) {
        int w = wsum[lane];
        int wi = w;
#pragma unroll
        for (int o = 1; o < 32; o <<= 1) {
            int n = __shfl_up_sync(FULL, wi, o);
            if (lane >= o) wi += n;
        }
        wsum[lane] = wi - w;
    }
    __syncthreads();
    int excl = g_boff[blockIdx.x] + wsum[wid] + (inc - v);
    if (idx < N_NODES) { g_off[idx] = excl; g_cursor[idx] = excl; }
    if (idx == 0) g_off[N_NODES] = E_EDGES;
}

// ---- fill CSR buckets (packed int2: src, weight-bits) ---------------------
__global__ void fill_kernel(const int* __restrict__ raw,
                            const float* __restrict__ ef) {
    int e = blockIdx.x * blockDim.x + threadIdx.x;
    if (e >= E_EDGES) return;
    int s, d;
    if (g_is64) {
        s = raw[2 * (size_t)e];
        d = raw[2 * ((size_t)E_EDGES + e)];
    } else {
        s = raw[e];
        d = raw[E_EDGES + e];
    }
    s = min(max(s, 0), N_NODES - 1);
    d = min(max(d, 0), N_NODES - 1);
    int pos = atomicAdd(&g_cursor[d], 1);
    g_edge[pos] = make_int2(s, __float_as_int(ef[e]));
}

// ---- GEMM (h = x @ W^T + b) fused with LN0 + ReLU, f32x2 FMA --------------
#define WS_PITCH 132
__global__ void gemm_ln_kernel(const float* __restrict__ x,
                               const float* __restrict__ W,
                               const float* __restrict__ b,
                               const float* __restrict__ scale,
                               const float* __restrict__ bias,
                               float* __restrict__ h_out,
                               __half* __restrict__ t_out) {
    extern __shared__ float4 smem[];
    float4* Ws = smem;                      // [k4][col] pitch WS_PITCH
    float4* Xs = smem + 32 * WS_PITCH;      // [warp*8 + r][k4]

    int tid = threadIdx.x, lane = tid & 31, warp = tid >> 5;
    int rowBase = blockIdx.x * 64 + warp * 8;

    for (int idx = tid; idx < DIM * 32; idx += 256) {
        int col = idx >> 5, k4 = idx & 31;
        Ws[k4 * WS_PITCH + col] = ((const float4*)W)[idx];
    }
    for (int r = 0; r < 8; r++) {
        int row = rowBase + r;
        float4 v = make_float4(0.f, 0.f, 0.f, 0.f);
        if (row < N_NODES) v = ((const float4*)x)[(size_t)row * 32 + lane];
        Xs[(warp * 8 + r) * 32 + lane] = v;
    }
    __syncthreads();

    unsigned long long acc2[8][4];
#pragma unroll
    for (int r = 0; r < 8; r++)
#pragma unroll
        for (int c = 0; c < 4; c++) acc2[r][c] = 0ull;

    for (int k4 = 0; k4 < 32; k4++) {
        unsigned long long xa[8], xb[8];
#pragma unroll
        for (int r = 0; r < 8; r++) {
            float4 xv = Xs[(warp * 8 + r) * 32 + k4];
            xa[r] = pack2(xv.x, xv.y);
            xb[r] = pack2(xv.z, xv.w);
        }
#pragma unroll
        for (int c = 0; c < 4; c++) {
            float4 wv = Ws[k4 * WS_PITCH + c * 32 + lane];
            unsigned long long wa = pack2(wv.x, wv.y);
            unsigned long long wb = pack2(wv.z, wv.w);
#pragma unroll
            for (int r = 0; r < 8; r++) {
                fma2(acc2[r][c], xa[r], wa);
                fma2(acc2[r][c], xb[r], wb);
            }
        }
    }

    float bv[4], sv[4], biv[4];
#pragma unroll
    for (int c = 0; c < 4; c++) {
        bv[c]  = __ldg(b + c * 32 + lane);
        sv[c]  = __ldg(scale + c * 32 + lane);
        biv[c] = __ldg(bias + c * 32 + lane);
    }

#pragma unroll
    for (int r = 0; r < 8; r++) {
        int row = rowBase + r;
        if (row >= N_NODES) break;
        float v[4];
#pragma unroll
        for (int c = 0; c < 4; c++) {
            float2 p = unpack2(acc2[r][c]);
            v[c] = p.x + p.y + bv[c];
        }
        float s = v[0] + v[1] + v[2] + v[3];
#pragma unroll
        for (int o = 16; o; o >>= 1) s += __shfl_xor_sync(FULL, s, o);
        float mu = s * (1.0f / 128.0f);
        float q = 0.f;
#pragma unroll
        for (int c = 0; c < 4; c++) {
            float d = v[c] - mu;
            q += d * d;
        }
#pragma unroll
        for (int o = 16; o; o >>= 1) q += __shfl_xor_sync(FULL, q, o);
        float rstd = rsqrtf(q * (1.0f / 128.0f) + 1e-5f);
        size_t base = (size_t)row * DIM;
#pragma unroll
        for (int c = 0; c < 4; c++) {
            h_out[base + c * 32 + lane] = v[c];
            float t = fmaf((v[c] - mu) * rstd, sv[c], biv[c]);
            t_out[base + c * 32 + lane] = __float2half_rn(fmaxf(t, 0.0f));
        }
    }
}

// ---- CSR aggregation, MLP-8 chunked gathers -------------------------------
#define CHUNK 8
template <bool FUSE_LN>
__global__ void agg_kernel(const __half* __restrict__ t,
                           const float* __restrict__ hres,
                           const float* __restrict__ scale,
                           const float* __restrict__ bias,
                           void* __restrict__ outp) {
    int warp = threadIdx.x >> 5;
    int lane = threadIdx.x & 31;
    int row = blockIdx.x * 8 + warp;
    if (row >= N_NODES) return;

    int beg = g_off[row], end = g_off[row + 1];
    float4 acc = make_float4(0.f, 0.f, 0.f, 0.f);

    int i = beg;
    for (; i + CHUNK <= end; i += CHUNK) {
        int2 eI[CHUNK];
#pragma unroll
        for (int j = 0; j < CHUNK; j++)
            eI[j] = __ldg(g_edge + i + j);     // warp-uniform 8B broadcast
        uint2 rv[CHUNK];
#pragma unroll
        for (int j = 0; j < CHUNK; j++)
            rv[j] = ((const uint2*)(t + (size_t)eI[j].x * DIM))[lane];
#pragma unroll
        for (int j = 0; j < CHUNK; j++) {
            float w = __int_as_float(eI[j].y);
            float2 f0 = __half22float2(*(const __half2*)&rv[j].x);
            float2 f1 = __half22float2(*(const __half2*)&rv[j].y);
            acc.x = fmaf(w, f0.x, acc.x);
            acc.y = fmaf(w, f0.y, acc.y);
            acc.z = fmaf(w, f1.x, acc.z);
            acc.w = fmaf(w, f1.y, acc.w);
        }
    }
    for (; i < end; i++) {
        int2 e = __ldg(g_edge + i);
        float w = __int_as_float(e.y);
        uint2 rv = ((const uint2*)(t + (size_t)e.x * DIM))[lane];
        float2 f0 = __half22float2(*(const __half2*)&rv.x);
        float2 f1 = __half22float2(*(const __half2*)&rv.y);
        acc.x = fmaf(w, f0.x, acc.x);
        acc.y = fmaf(w, f0.y, acc.y);
        acc.z = fmaf(w, f1.x, acc.z);
        acc.w = fmaf(w, f1.y, acc.w);
    }

    size_t base = (size_t)row * DIM;
    if (FUSE_LN) {
        float4 o = ((const float4*)(hres + base))[lane];
        acc.x += o.x; acc.y += o.y; acc.z += o.z; acc.w += o.w;
        float s = acc.x + acc.y + acc.z + acc.w;
#pragma unroll
        for (int o2 = 16; o2; o2 >>= 1) s += __shfl_xor_sync(FULL, s, o2);
        float mu = s * (1.0f / 128.0f);
        float dx = acc.x - mu, dy = acc.y - mu, dz = acc.z - mu, dw = acc.w - mu;
        float q = dx * dx + dy * dy + dz * dz + dw * dw;
#pragma unroll
        for (int o2 = 16; o2; o2 >>= 1) q += __shfl_xor_sync(FULL, q, o2);
        float rstd = rsqrtf(q * (1.0f / 128.0f) + 1e-5f);
        float4 sc = ((const float4*)scale)[lane];
        float4 bi = ((const float4*)bias)[lane];
        float rx = fmaxf(fmaf(dx * rstd, sc.x, bi.x), 0.0f);
        float ry = fmaxf(fmaf(dy * rstd, sc.y, bi.y), 0.0f);
        float rz = fmaxf(fmaf(dz * rstd, sc.z, bi.z), 0.0f);
        float rw = fmaxf(fmaf(dw * rstd, sc.w, bi.w), 0.0f);
        uint2 st;
        *(__half2*)&st.x = __floats2half2_rn(rx, ry);
        *(__half2*)&st.y = __floats2half2_rn(rz, rw);
        ((uint2*)((__half*)outp + base))[lane] = st;
    } else {
        ((float4*)((float*)outp + base))[lane] = acc;
    }
}

extern "C" void kernel_launch(void* const* d_in, const int* in_sizes, int n_in,
                              void* d_out, int out_size) {
    const float* x = nullptr;
    const int*   ei_raw = nullptr;
    const float* ef = nullptr;
    const float* lin_w = nullptr;
    const float* lin_b = nullptr;
    const float* ln_scale = nullptr;
    const float* ln_bias = nullptr;
    for (int i = 0; i < n_in; i++) {
        switch (in_sizes[i]) {
            case N_NODES * DIM: x      = (const float*)d_in[i]; break;
            case 2 * E_EDGES:   ei_raw = (const int*)d_in[i];   break;
            case E_EDGES:       ef     = (const float*)d_in[i]; break;
            case DIM * DIM:     lin_w  = (const float*)d_in[i]; break;
            case DIM:           lin_b  = (const float*)d_in[i]; break;
            case 2 * DIM:
                if (!ln_scale) ln_scale = (const float*)d_in[i];
                else           ln_bias  = (const float*)d_in[i];
                break;
            default: break;
        }
    }
    float* out = (float*)d_out;

    float  *h;
    __half *t, *t2;
    cudaGetSymbolAddress((void**)&h,  g_h);
    cudaGetSymbolAddress((void**)&t,  g_t);
    cudaGetSymbolAddress((void**)&t2, g_t2);

    const int EDGE_BLKS = (E_EDGES + 255) / 256;
    const int NODE_BLKS = (N_NODES + 255) / 256;
    const int ROWS_GRID = (N_NODES + 7) / 8;
    const int GEMM_GRID = (N_NODES + 63) / 64;
    const int GEMM_SMEM = (32 * WS_PITCH + 8 * 8 * 32) * sizeof(float4);

    // one-time setup: happens on the first (non-captured) correctness call
    static cudaStream_t s_side = nullptr;
    static cudaEvent_t  ev_fork = nullptr, ev_join = nullptr;
    static bool init_done = false;
    if (!init_done) {
        cudaFuncSetAttribute(gemm_ln_kernel,
                             cudaFuncAttributeMaxDynamicSharedMemorySize,
                             GEMM_SMEM);
        if (cudaStreamCreateWithFlags(&s_side, cudaStreamNonBlocking) !=
            cudaSuccess) s_side = nullptr;
        if (s_side) {
            cudaEventCreateWithFlags(&ev_fork, cudaEventDisableTiming);
            cudaEventCreateWithFlags(&ev_join, cudaEventDisableTiming);
        }
        init_done = true;
    }

    if (s_side) {
        // fork: GEMM+LN0 on side stream, CSR build on main stream
        cudaEventRecord(ev_fork, 0);
        cudaStreamWaitEvent(s_side, ev_fork, 0);
        gemm_ln_kernel<<<GEMM_GRID, 256, GEMM_SMEM, s_side>>>(
            x, lin_w, lin_b, ln_scale, ln_bias, h, t);
        cudaEventRecord(ev_join, s_side);

        detect_kernel<<<1, 32>>>(ei_raw);
        zero_deg_kernel<<<NODE_BLKS, 256>>>();
        hist_kernel<<<EDGE_BLKS, 256>>>(ei_raw);
        block_sum_kernel<<<SCAN_BLOCKS, 1024>>>();
        bsum_scan_kernel<<<1, 128>>>();
        scan_apply_kernel<<<SCAN_BLOCKS, 1024>>>();
        fill_kernel<<<EDGE_BLKS, 256>>>(ei_raw, ef);

        cudaStreamWaitEvent(0, ev_join, 0);   // join before agg0
    } else {
        // fallback: fully sequential
        detect_kernel<<<1, 32>>>(ei_raw);
        zero_deg_kernel<<<NODE_BLKS, 256>>>();
        hist_kernel<<<EDGE_BLKS, 256>>>(ei_raw);
        block_sum_kernel<<<SCAN_BLOCKS, 1024>>>();
        bsum_scan_kernel<<<1, 128>>>();
        scan_apply_kernel<<<SCAN_BLOCKS, 1024>>>();
        fill_kernel<<<EDGE_BLKS, 256>>>(ei_raw, ef);
        gemm_ln_kernel<<<GEMM_GRID, 256, GEMM_SMEM>>>(
            x, lin_w, lin_b, ln_scale, ln_bias, h, t);
    }

    // ---- layer 0 agg + residual + LN1 + ReLU -> t2 (fp16) ----
    agg_kernel<true><<<ROWS_GRID, 256>>>(t, h, ln_scale + DIM, ln_bias + DIM,
                                         (void*)t2);

    // ---- layer 1 agg -> out (fp32) ----
    agg_kernel<false><<<ROWS_GRID, 256>>>(t2, nullptr, nullptr, nullptr,
                                          (void*)out);
}